// round 15
// baseline (speedup 1.0000x reference)
#include <cuda_runtime.h>
#include <cuda_fp16.h>
#include <math.h>
#include <stdint.h>

// ---------------- problem constants ----------------
#define BATCH   2
#define SEQLEN  2048
#define DMODEL  4096
#define NHEADS  32
#define NKV     8
#define HD      128
#define QDIM    (NHEADS * HD)            // 4096
#define KVDIM   (NKV * HD)               // 1024
#define QKVDIM  (QDIM + 2 * KVDIM)       // 6144
#define MROWS   (BATCH * SEQLEN)         // 4096

// ---------------- scratch (device globals: allocation-free) ----------------
__device__ __half g_xh[(size_t)MROWS * DMODEL];
__device__ __half g_wqkvh[(size_t)QKVDIM * DMODEL];
__device__ __half g_woh[(size_t)DMODEL * DMODEL];
__device__ __half g_ah[(size_t)MROWS * DMODEL];
__device__ __half g_qh[(size_t)MROWS * QKVDIM];   // rope'd qkv (fp16)

// ---------------- helpers ----------------
__device__ __forceinline__ uint32_t smem_to_u32(const void* smem_ptr) {
    uint32_t addr;
    asm("{ .reg .u64 tmp; cvta.to.shared.u64 tmp, %1; cvt.u32.u64 %0, tmp; }"
        : "=r"(addr) : "l"(smem_ptr));
    return addr;
}
__device__ __forceinline__ void cp_async16(uint32_t dst, const void* src) {
    asm volatile("cp.async.cg.shared.global [%0], [%1], 16;\n"
                 :: "r"(dst), "l"(src));
}
__device__ __forceinline__ void cp_commit() {
    asm volatile("cp.async.commit_group;\n" ::: "memory");
}
__device__ __forceinline__ void cp_wait0() {
    asm volatile("cp.async.wait_group 0;\n" ::: "memory");
}
__device__ __forceinline__ void cp_wait1() {
    asm volatile("cp.async.wait_group 1;\n" ::: "memory");
}
__device__ __forceinline__ void ldm_x4(uint32_t* r, uint32_t a) {
    asm volatile("ldmatrix.sync.aligned.m8n8.x4.shared.b16 {%0,%1,%2,%3}, [%4];"
                 : "=r"(r[0]), "=r"(r[1]), "=r"(r[2]), "=r"(r[3]) : "r"(a));
}
__device__ __forceinline__ void ldm_x4_t(uint32_t* r, uint32_t a) {
    asm volatile("ldmatrix.sync.aligned.m8n8.x4.trans.shared.b16 {%0,%1,%2,%3}, [%4];"
                 : "=r"(r[0]), "=r"(r[1]), "=r"(r[2]), "=r"(r[3]) : "r"(a));
}
__device__ __forceinline__ void mma_fp16(float* c, const uint32_t* a,
                                         uint32_t b0, uint32_t b1) {
    asm volatile(
        "mma.sync.aligned.m16n8k16.row.col.f32.f16.f16.f32 "
        "{%0,%1,%2,%3}, {%4,%5,%6,%7}, {%8,%9}, {%0,%1,%2,%3};"
        : "+f"(c[0]), "+f"(c[1]), "+f"(c[2]), "+f"(c[3])
        : "r"(a[0]), "r"(a[1]), "r"(a[2]), "r"(a[3]), "r"(b0), "r"(b1));
}
__device__ __forceinline__ float ex2f(float x) {
    float y;
    asm("ex2.approx.f32 %0, %1;" : "=f"(y) : "f"(x));
    return y;
}
__device__ __forceinline__ uint32_t pack_fp16(float f0, float f1) {
    uint16_t b0 = __half_as_ushort(__float2half_rn(f0));
    uint16_t b1 = __half_as_ushort(__float2half_rn(f1));
    return ((uint32_t)b1 << 16) | (uint32_t)b0;
}

// ============================================================
// HMMA GEMM v7 (fp16): C = Ah[M,K] @ Bh[N,K]^T + bias
// 128 threads (4 warps 2x2, warp tile 64x64), CTA tile 128x128,
// BK=64, XOR-swizzled smem, 3-stage pipeline, 2 CTAs per SM.
// Fragment reuse 4x both sides -> LDSM traffic 128 B/MMA.
// ============================================================
#define HBM 128
#define HBN 128
#define HBK 64
// row = 64 halves = 128 B, 8 chunks of 16B, swizzle: chunk ^= (row & 7)
#define OFF_B (128 * 128)               // 16384
#define STAGE_B (256 * 128)             // 32768
#define HSMEM (3 * STAGE_B)             // 98304

__device__ __forceinline__ uint32_t sw_off(int row, int chunk) {
    return (uint32_t)(row * 128 + ((chunk ^ (row & 7)) << 4));
}

__device__ __forceinline__ void gemm_load_stage(
    const __half* __restrict__ Ah, const __half* __restrict__ Bh,
    uint32_t sbase, int bm, int bn, int k0, int K, int tid)
{
    // A: 128 rows x 8 chunks = 1024 -> 8 iters of 128
    #pragma unroll
    for (int l = 0; l < 8; l++) {
        int u = tid + l * 128;
        int r = u >> 3, g = u & 7;
        size_t goff = (size_t)(bm + r) * K + k0 + g * 8;
        cp_async16(sbase + sw_off(r, g), Ah + goff);
    }
    // B: 128 rows x 8 chunks = 1024 -> 8 iters
    #pragma unroll
    for (int l = 0; l < 8; l++) {
        int u = tid + l * 128;
        int r = u >> 3, g = u & 7;
        size_t goff = (size_t)(bn + r) * K + k0 + g * 8;
        cp_async16(sbase + OFF_B + sw_off(r, g), Bh + goff);
    }
}

template <bool FUSE_ROPE>
__global__ __launch_bounds__(128, 2) void hmma_gemm_kernel(
    const __half* __restrict__ Ah, const __half* __restrict__ Bh,
    const float* __restrict__ bias,
    float* __restrict__ C32, __half* __restrict__ C16,
    int M, int N, int K)
{
    extern __shared__ char smem[];
    const uint32_t sb = smem_to_u32(smem);
    const int tid = threadIdx.x;
    const int lane = tid & 31, wid = tid >> 5;
    const int wm = wid & 1;        // 2 warp rows (64 m each)
    const int wn = wid >> 1;       // 2 warp cols (64 n each)
    const int bm = blockIdx.y * HBM;
    const int bn = blockIdx.x * HBN;

    float acc[4][8][4];
    #pragma unroll
    for (int i = 0; i < 4; i++)
        #pragma unroll
        for (int j = 0; j < 8; j++)
            #pragma unroll
            for (int v = 0; v < 4; v++) acc[i][j][v] = 0.f;

    const int NC = K / HBK;   // 64

    gemm_load_stage(Ah, Bh, sb, bm, bn, 0, K, tid);
    cp_commit();
    gemm_load_stage(Ah, Bh, sb + STAGE_B, bm, bn, HBK, K, tid);
    cp_commit();

    const int arow0 = wm * 64 + (lane & 15);   // + mt*16
    const int brow0 = wn * 64 + (lane & 15);   // + nb*16
    const int khalf = lane >> 4;

    int st = 0;
    for (int c = 0; c < NC; c++) {
        if (c + 2 < NC) cp_wait1(); else cp_wait0();
        __syncthreads();

        if (c + 2 < NC) {
            int st2 = st + 2; if (st2 >= 3) st2 -= 3;
            gemm_load_stage(Ah, Bh, sb + st2 * STAGE_B,
                            bm, bn, (c + 2) * HBK, K, tid);
            cp_commit();
        }

        const uint32_t base = sb + st * STAGE_B;
        #pragma unroll
        for (int ks = 0; ks < 4; ks++) {
            const int chunk = ks * 2 + khalf;
            uint32_t A0[4][4], B0[4][4];
            #pragma unroll
            for (int mt = 0; mt < 4; mt++)
                ldm_x4(A0[mt], base + sw_off(arow0 + mt * 16, chunk));
            #pragma unroll
            for (int nb = 0; nb < 4; nb++)
                ldm_x4(B0[nb], base + OFF_B + sw_off(brow0 + nb * 16, chunk));

            #pragma unroll
            for (int mt = 0; mt < 4; mt++)
                #pragma unroll
                for (int nb = 0; nb < 4; nb++) {
                    mma_fp16(acc[mt][2 * nb],     A0[mt], B0[nb][0], B0[nb][2]);
                    mma_fp16(acc[mt][2 * nb + 1], A0[mt], B0[nb][1], B0[nb][3]);
                }
        }
        if (++st == 3) st = 0;
    }

    // ---------------- epilogue ----------------
    #pragma unroll
    for (int mt = 0; mt < 4; mt++) {
        const int row0 = bm + wm * 64 + mt * 16 + (lane >> 2);
        #pragma unroll
        for (int nt = 0; nt < 8; nt++) {
            const int col = bn + wn * 64 + nt * 8 + (lane & 3) * 2;
            const float b0 = bias[col], b1 = bias[col + 1];
            float a0 = acc[mt][nt][0] + b0, a1 = acc[mt][nt][1] + b1;
            float a2 = acc[mt][nt][2] + b0, a3 = acc[mt][nt][3] + b1;
            if (FUSE_ROPE) {
                if (col < QDIM + KVDIM) {
                    const int p = (col & 127) >> 1;
                    const float inv_freq =
                        exp2f(-(float)(2 * p) * (13.287712379549449f / 128.f));
                    {
                        float s = (float)(row0 & (SEQLEN - 1));
                        float cc, sn; sincosf(s * inv_freq, &sn, &cc);
                        float r0 = a0 * cc - a1 * sn;
                        float r1 = a0 * sn + a1 * cc;
                        a0 = r0; a1 = r1;
                    }
                    {
                        float s = (float)((row0 + 8) & (SEQLEN - 1));
                        float cc, sn; sincosf(s * inv_freq, &sn, &cc);
                        float r0 = a2 * cc - a3 * sn;
                        float r1 = a2 * sn + a3 * cc;
                        a2 = r0; a3 = r1;
                    }
                }
                *(uint32_t*)(C16 + (size_t)row0 * N + col) = pack_fp16(a0, a1);
                *(uint32_t*)(C16 + (size_t)(row0 + 8) * N + col) = pack_fp16(a2, a3);
            } else {
                *(float2*)(C32 + (size_t)row0 * N + col) = make_float2(a0, a1);
                *(float2*)(C32 + (size_t)(row0 + 8) * N + col) = make_float2(a2, a3);
            }
        }
    }
}

// ============================================================
// fp32 -> fp16 convert
// ============================================================
__global__ void convert_fp16_kernel(const float* __restrict__ src,
                                    __half* __restrict__ hi, int n4)
{
    int i = blockIdx.x * blockDim.x + threadIdx.x;
    if (i >= n4) return;
    float4 v = ((const float4*)src)[i];
    __half2* hp = (__half2*)hi;
    hp[2 * i]     = __halves2half2(__float2half_rn(v.x), __float2half_rn(v.y));
    hp[2 * i + 1] = __halves2half2(__float2half_rn(v.z), __float2half_rn(v.w));
}

// ============================================================
// HMMA flash attention (fp16 single-pass), 2 CTAs/SM:
// Br=128 (8 warps x 16 rows), Bc=64.
// scores = Qh·Kh ; O += Ph·Vh. Output -> fp16.
// Heavy (large-qb) tiles scheduled first via index reversal.
// ============================================================
#define QROWB 272
#define FA_QH  0
#define FA_ST0 34816
#define FA_STB 34816          // Kh + Vh per stage
#define FA_KH  0
#define FA_VH  17408
#define FA_SMEM (34816 + 2 * 34816)   // 104448

__global__ __launch_bounds__(256, 2) void fa_hmma_kernel(
    const __half* __restrict__ qh, __half* __restrict__ oh)
{
    extern __shared__ char smem[];
    const uint32_t sb = smem_to_u32(smem);
    const int tid = threadIdx.x;
    const int lane = tid & 31, w = tid >> 5;
    const int b = blockIdx.z, h = blockIdx.y;
    const int qb = gridDim.x - 1 - blockIdx.x;   // heavy tiles first
    const int kvh = h >> 2;
    const int q0 = qb * 128;
    const int rowbase = b * SEQLEN;

    // Q tile: 128 rows x 16 chunks = 2048 -> 8 iters
    #pragma unroll
    for (int l = 0; l < 8; l++) {
        int u = tid + l * 256;
        int r = (u >> 4) & 127;
        int ch = u & 15;
        const __half* src = qh +
            (size_t)(rowbase + q0 + r) * QKVDIM + h * HD + ch * 8;
        cp_async16(sb + FA_QH + r * QROWB + ch * 16, src);
    }
    // KV stage: Kh + Vh = 2048 chunks -> 8 iters
    auto load_kv = [&](int t, int s) {
        const int k0 = t * 64;
        const uint32_t stb = sb + FA_ST0 + s * FA_STB;
        #pragma unroll
        for (int l = 0; l < 8; l++) {
            int u = tid + l * 256;
            int sel = u >> 10;            // 0 Kh, 1 Vh
            int r = (u >> 4) & 63;
            int ch = u & 15;
            int gcol = sel ? (QDIM + KVDIM + kvh * HD) : (QDIM + kvh * HD);
            const __half* src = qh +
                (size_t)(rowbase + k0 + r) * QKVDIM + gcol + ch * 8;
            cp_async16(stb + sel * 17408 + r * QROWB + ch * 16, src);
        }
    };

    const int tmax = 2 * qb + 2;
    load_kv(0, 0);
    cp_commit();

    const float CEXP = 0.12751742f;       // (1/sqrt(128)) * log2(e)
    float m2[2] = {-1e30f, -1e30f};
    float l2[2] = {0.f, 0.f};
    float O[16][4];
    #pragma unroll
    for (int i = 0; i < 16; i++)
        #pragma unroll
        for (int v = 0; v < 4; v++) O[i][v] = 0.f;

    const int qrow0 = q0 + w * 16;

    for (int t = 0; t < tmax; t++) {
        if (t + 1 < tmax) load_kv(t + 1, (t + 1) & 1);
        cp_commit();
        cp_wait1();
        __syncthreads();

        const int k0 = t * 64;
        const uint32_t stb = sb + FA_ST0 + (t & 1) * FA_STB;

        if (k0 <= qrow0 + 15) {
            // ---------- scores S = Qh Kh^T ----------
            float S[8][4];
            #pragma unroll
            for (int i = 0; i < 8; i++)
                #pragma unroll
                for (int v = 0; v < 4; v++) S[i][v] = 0.f;

            const uint32_t qa = sb + FA_QH + (w * 16 + (lane & 15)) * QROWB +
                                ((lane >> 4) * 16);
            const uint32_t ka = stb + FA_KH + ((lane & 15)) * QROWB +
                                ((lane >> 4) * 16);
            #pragma unroll
            for (int kc = 0; kc < 8; kc++) {
                uint32_t A0[4];
                ldm_x4(A0, qa + kc * 32);
                #pragma unroll
                for (int g = 0; g < 4; g++) {
                    uint32_t B[4];
                    ldm_x4(B, ka + kc * 32 + g * 16 * QROWB);
                    mma_fp16(S[2 * g],     A0, B[0], B[2]);
                    mma_fp16(S[2 * g + 1], A0, B[1], B[3]);
                }
            }

            // ---------- causal mask ----------
            if (k0 + 63 > qrow0) {
                const int r0 = qrow0 + (lane >> 2);
                #pragma unroll
                for (int nt = 0; nt < 8; nt++) {
                    const int c0 = k0 + nt * 8 + (lane & 3) * 2;
                    if (c0     > r0)     S[nt][0] = -1e30f;
                    if (c0 + 1 > r0)     S[nt][1] = -1e30f;
                    if (c0     > r0 + 8) S[nt][2] = -1e30f;
                    if (c0 + 1 > r0 + 8) S[nt][3] = -1e30f;
                }
            }

            // ---------- online softmax ----------
            #pragma unroll
            for (int r = 0; r < 2; r++) {
                const int i0 = r * 2;
                float rmax = -1e30f;
                #pragma unroll
                for (int nt = 0; nt < 8; nt++)
                    rmax = fmaxf(rmax, fmaxf(S[nt][i0], S[nt][i0 + 1]));
                rmax = fmaxf(rmax, __shfl_xor_sync(0xffffffffu, rmax, 1));
                rmax = fmaxf(rmax, __shfl_xor_sync(0xffffffffu, rmax, 2));
                const float mnew = fmaxf(m2[r], rmax);
                const float corr = ex2f((m2[r] - mnew) * CEXP);
                m2[r] = mnew;
                float psum = 0.f;
                #pragma unroll
                for (int nt = 0; nt < 8; nt++) {
                    float p0 = ex2f((S[nt][i0]     - mnew) * CEXP);
                    float p1 = ex2f((S[nt][i0 + 1] - mnew) * CEXP);
                    S[nt][i0] = p0; S[nt][i0 + 1] = p1;
                    psum += p0 + p1;
                }
                psum += __shfl_xor_sync(0xffffffffu, psum, 1);
                psum += __shfl_xor_sync(0xffffffffu, psum, 2);
                l2[r] = l2[r] * corr + psum;
                #pragma unroll
                for (int nt = 0; nt < 16; nt++) {
                    O[nt][i0]     *= corr;
                    O[nt][i0 + 1] *= corr;
                }
            }

            // ---------- PV: O += Ph Vh ----------
            #pragma unroll
            for (int j = 0; j < 4; j++) {
                uint32_t Ph[4];
                #pragma unroll
                for (int q = 0; q < 2; q++) {
                    const int nt = 2 * j + q;
                    Ph[2 * q]     = pack_fp16(S[nt][0], S[nt][1]);
                    Ph[2 * q + 1] = pack_fp16(S[nt][2], S[nt][3]);
                }
                const int vrow = j * 16 + (lane & 7) + ((lane >> 3) & 1) * 8;
                #pragma unroll
                for (int n = 0; n < 8; n++) {
                    uint32_t va = stb + FA_VH + vrow * QROWB +
                                  (n * 16 + (lane >> 4) * 8) * 2;
                    uint32_t Bv[4];
                    ldm_x4_t(Bv, va);
                    mma_fp16(O[2 * n],     Ph, Bv[0], Bv[1]);
                    mma_fp16(O[2 * n + 1], Ph, Bv[2], Bv[3]);
                }
            }
        }
        __syncthreads();
    }

    // ---------- epilogue: normalize, convert to fp16 ----------
    #pragma unroll
    for (int r = 0; r < 2; r++) {
        float inv = 1.0f / l2[r];
        const int row = rowbase + qrow0 + (lane >> 2) + r * 8;
        const size_t off = (size_t)row * DMODEL + h * HD + (lane & 3) * 2;
        #pragma unroll
        for (int nt = 0; nt < 16; nt++) {
            float f0 = O[nt][2 * r] * inv;
            float f1 = O[nt][2 * r + 1] * inv;
            *(uint32_t*)(oh + off + nt * 8) = pack_fp16(f0, f1);
        }
    }
}

// ============================================================
// launch
// ============================================================
extern "C" void kernel_launch(void* const* d_in, const int* in_sizes, int n_in,
                              void* d_out, int out_size)
{
    (void)in_sizes; (void)n_in; (void)out_size;
    const float* x      = (const float*)d_in[0];
    const float* w_qkv  = (const float*)d_in[1];
    const float* b_qkv  = (const float*)d_in[2];
    const float* w_o    = (const float*)d_in[3];
    const float* b_o    = (const float*)d_in[4];
    float* out = (float*)d_out;

    __half *xh, *wqh, *woh, *ah, *qh;
    cudaGetSymbolAddress((void**)&xh,  g_xh);
    cudaGetSymbolAddress((void**)&wqh, g_wqkvh);
    cudaGetSymbolAddress((void**)&woh, g_woh);
    cudaGetSymbolAddress((void**)&ah,  g_ah);
    cudaGetSymbolAddress((void**)&qh,  g_qh);

    cudaFuncSetAttribute(hmma_gemm_kernel<true>,
                         cudaFuncAttributeMaxDynamicSharedMemorySize, HSMEM);
    cudaFuncSetAttribute(hmma_gemm_kernel<false>,
                         cudaFuncAttributeMaxDynamicSharedMemorySize, HSMEM);
    cudaFuncSetAttribute(fa_hmma_kernel,
                         cudaFuncAttributeMaxDynamicSharedMemorySize, FA_SMEM);

    // 0) convert x and weights to fp16
    {
        int n4 = (MROWS * DMODEL) / 4;
        convert_fp16_kernel<<<n4 / 256, 256>>>(x, xh, n4);
        int w4 = (QKVDIM * DMODEL) / 4;
        convert_fp16_kernel<<<w4 / 256, 256>>>(w_qkv, wqh, w4);
        int o4 = (DMODEL * DMODEL) / 4;
        convert_fp16_kernel<<<o4 / 256, 256>>>(w_o, woh, o4);
    }

    // 1) QKV projection + fused bias/RoPE/fp16 -> g_qh
    hmma_gemm_kernel<true><<<dim3(QKVDIM / HBN, MROWS / HBM), 128, HSMEM>>>(
        xh, wqh, b_qkv, nullptr, qh, MROWS, QKVDIM, DMODEL);

    // 2) fp16 flash attention -> g_ah (fp16)
    fa_hmma_kernel<<<dim3(SEQLEN / 128, NHEADS, BATCH), 256, FA_SMEM>>>(
        qh, ah);

    // 3) O projection (fp16) -> fp32 out
    hmma_gemm_kernel<false><<<dim3(DMODEL / HBN, MROWS / HBM), 128, HSMEM>>>(
        ah, woh, b_o, out, nullptr, MROWS, DMODEL, DMODEL);
}

// round 16
// speedup vs baseline: 1.0184x; 1.0184x over previous
#include <cuda_runtime.h>
#include <cuda_fp16.h>
#include <math.h>
#include <stdint.h>

// ---------------- problem constants ----------------
#define BATCH   2
#define SEQLEN  2048
#define DMODEL  4096
#define NHEADS  32
#define NKV     8
#define HD      128
#define QDIM    (NHEADS * HD)            // 4096
#define KVDIM   (NKV * HD)               // 1024
#define QKVDIM  (QDIM + 2 * KVDIM)       // 6144
#define MROWS   (BATCH * SEQLEN)         // 4096

// ---------------- scratch (device globals: allocation-free) ----------------
__device__ __half g_xh[(size_t)MROWS * DMODEL];
__device__ __half g_wqkvh[(size_t)QKVDIM * DMODEL];
__device__ __half g_woh[(size_t)DMODEL * DMODEL];
__device__ __half g_ah[(size_t)MROWS * DMODEL];
__device__ __half g_qh[(size_t)MROWS * QKVDIM];   // rope'd qkv (fp16)

// ---------------- helpers ----------------
__device__ __forceinline__ uint32_t smem_to_u32(const void* smem_ptr) {
    uint32_t addr;
    asm("{ .reg .u64 tmp; cvta.to.shared.u64 tmp, %1; cvt.u32.u64 %0, tmp; }"
        : "=r"(addr) : "l"(smem_ptr));
    return addr;
}
__device__ __forceinline__ void cp_async16(uint32_t dst, const void* src) {
    asm volatile("cp.async.cg.shared.global [%0], [%1], 16;\n"
                 :: "r"(dst), "l"(src));
}
__device__ __forceinline__ void cp_commit() {
    asm volatile("cp.async.commit_group;\n" ::: "memory");
}
__device__ __forceinline__ void cp_wait0() {
    asm volatile("cp.async.wait_group 0;\n" ::: "memory");
}
__device__ __forceinline__ void cp_wait1() {
    asm volatile("cp.async.wait_group 1;\n" ::: "memory");
}
__device__ __forceinline__ void ldm_x4(uint32_t* r, uint32_t a) {
    asm volatile("ldmatrix.sync.aligned.m8n8.x4.shared.b16 {%0,%1,%2,%3}, [%4];"
                 : "=r"(r[0]), "=r"(r[1]), "=r"(r[2]), "=r"(r[3]) : "r"(a));
}
__device__ __forceinline__ void ldm_x4_t(uint32_t* r, uint32_t a) {
    asm volatile("ldmatrix.sync.aligned.m8n8.x4.trans.shared.b16 {%0,%1,%2,%3}, [%4];"
                 : "=r"(r[0]), "=r"(r[1]), "=r"(r[2]), "=r"(r[3]) : "r"(a));
}
__device__ __forceinline__ void mma_fp16(float* c, const uint32_t* a,
                                         uint32_t b0, uint32_t b1) {
    asm volatile(
        "mma.sync.aligned.m16n8k16.row.col.f32.f16.f16.f32 "
        "{%0,%1,%2,%3}, {%4,%5,%6,%7}, {%8,%9}, {%0,%1,%2,%3};"
        : "+f"(c[0]), "+f"(c[1]), "+f"(c[2]), "+f"(c[3])
        : "r"(a[0]), "r"(a[1]), "r"(a[2]), "r"(a[3]), "r"(b0), "r"(b1));
}
__device__ __forceinline__ float ex2f(float x) {
    float y;
    asm("ex2.approx.f32 %0, %1;" : "=f"(y) : "f"(x));
    return y;
}
__device__ __forceinline__ uint32_t pack_fp16(float f0, float f1) {
    uint16_t b0 = __half_as_ushort(__float2half_rn(f0));
    uint16_t b1 = __half_as_ushort(__float2half_rn(f1));
    return ((uint32_t)b1 << 16) | (uint32_t)b0;
}

// ============================================================
// HMMA GEMM v8 (fp16): C = Ah[M,K] @ Bh[N,K]^T + bias
// 128 threads (4 warps 2x2, warp tile 64x32), CTA tile 128x64,
// BK=64, XOR-swizzled smem, 3-stage pipeline, 3 CTAs per SM.
// Combines v6's occupancy (12 warps/SM) with v7's A-side reuse.
// ============================================================
#define HBM 128
#define HBN 64
#define HBK 64
// row = 64 halves = 128 B, 8 chunks of 16B, swizzle: chunk ^= (row & 7)
#define OFF_B (128 * 128)               // 16384
#define STAGE_B ((128 + 64) * 128)      // 24576
#define HSMEM (3 * STAGE_B)             // 73728

__device__ __forceinline__ uint32_t sw_off(int row, int chunk) {
    return (uint32_t)(row * 128 + ((chunk ^ (row & 7)) << 4));
}

__device__ __forceinline__ void gemm_load_stage(
    const __half* __restrict__ Ah, const __half* __restrict__ Bh,
    uint32_t sbase, int bm, int bn, int k0, int K, int tid)
{
    // A: 128 rows x 8 chunks = 1024 -> 8 iters of 128
    #pragma unroll
    for (int l = 0; l < 8; l++) {
        int u = tid + l * 128;
        int r = u >> 3, g = u & 7;
        size_t goff = (size_t)(bm + r) * K + k0 + g * 8;
        cp_async16(sbase + sw_off(r, g), Ah + goff);
    }
    // B: 64 rows x 8 chunks = 512 -> 4 iters
    #pragma unroll
    for (int l = 0; l < 4; l++) {
        int u = tid + l * 128;
        int r = u >> 3, g = u & 7;
        size_t goff = (size_t)(bn + r) * K + k0 + g * 8;
        cp_async16(sbase + OFF_B + sw_off(r, g), Bh + goff);
    }
}

template <bool FUSE_ROPE>
__global__ __launch_bounds__(128, 3) void hmma_gemm_kernel(
    const __half* __restrict__ Ah, const __half* __restrict__ Bh,
    const float* __restrict__ bias,
    float* __restrict__ C32, __half* __restrict__ C16,
    int M, int N, int K)
{
    extern __shared__ char smem[];
    const uint32_t sb = smem_to_u32(smem);
    const int tid = threadIdx.x;
    const int lane = tid & 31, wid = tid >> 5;
    const int wm = wid & 1;        // 2 warp rows (64 m each)
    const int wn = wid >> 1;       // 2 warp cols (32 n each)
    const int bm = blockIdx.y * HBM;
    const int bn = blockIdx.x * HBN;

    float acc[4][4][4];
    #pragma unroll
    for (int i = 0; i < 4; i++)
        #pragma unroll
        for (int j = 0; j < 4; j++)
            #pragma unroll
            for (int v = 0; v < 4; v++) acc[i][j][v] = 0.f;

    const int NC = K / HBK;   // 64

    gemm_load_stage(Ah, Bh, sb, bm, bn, 0, K, tid);
    cp_commit();
    gemm_load_stage(Ah, Bh, sb + STAGE_B, bm, bn, HBK, K, tid);
    cp_commit();

    const int arow0 = wm * 64 + (lane & 15);   // + mt*16
    const int brow0 = wn * 32 + (lane & 15);   // + nb*16
    const int khalf = lane >> 4;

    int st = 0;
    for (int c = 0; c < NC; c++) {
        if (c + 2 < NC) cp_wait1(); else cp_wait0();
        __syncthreads();

        if (c + 2 < NC) {
            int st2 = st + 2; if (st2 >= 3) st2 -= 3;
            gemm_load_stage(Ah, Bh, sb + st2 * STAGE_B,
                            bm, bn, (c + 2) * HBK, K, tid);
            cp_commit();
        }

        const uint32_t base = sb + st * STAGE_B;
        #pragma unroll
        for (int ks = 0; ks < 4; ks++) {
            const int chunk = ks * 2 + khalf;
            uint32_t A0[4][4], B0[2][4];
            #pragma unroll
            for (int mt = 0; mt < 4; mt++)
                ldm_x4(A0[mt], base + sw_off(arow0 + mt * 16, chunk));
            #pragma unroll
            for (int nb = 0; nb < 2; nb++)
                ldm_x4(B0[nb], base + OFF_B + sw_off(brow0 + nb * 16, chunk));

            #pragma unroll
            for (int mt = 0; mt < 4; mt++)
                #pragma unroll
                for (int nb = 0; nb < 2; nb++) {
                    mma_fp16(acc[mt][2 * nb],     A0[mt], B0[nb][0], B0[nb][2]);
                    mma_fp16(acc[mt][2 * nb + 1], A0[mt], B0[nb][1], B0[nb][3]);
                }
        }
        if (++st == 3) st = 0;
    }

    // ---------------- epilogue ----------------
    #pragma unroll
    for (int mt = 0; mt < 4; mt++) {
        const int row0 = bm + wm * 64 + mt * 16 + (lane >> 2);
        #pragma unroll
        for (int nt = 0; nt < 4; nt++) {
            const int col = bn + wn * 32 + nt * 8 + (lane & 3) * 2;
            const float b0 = bias[col], b1 = bias[col + 1];
            float a0 = acc[mt][nt][0] + b0, a1 = acc[mt][nt][1] + b1;
            float a2 = acc[mt][nt][2] + b0, a3 = acc[mt][nt][3] + b1;
            if (FUSE_ROPE) {
                if (col < QDIM + KVDIM) {
                    const int p = (col & 127) >> 1;
                    const float inv_freq =
                        exp2f(-(float)(2 * p) * (13.287712379549449f / 128.f));
                    {
                        float s = (float)(row0 & (SEQLEN - 1));
                        float cc, sn; sincosf(s * inv_freq, &sn, &cc);
                        float r0 = a0 * cc - a1 * sn;
                        float r1 = a0 * sn + a1 * cc;
                        a0 = r0; a1 = r1;
                    }
                    {
                        float s = (float)((row0 + 8) & (SEQLEN - 1));
                        float cc, sn; sincosf(s * inv_freq, &sn, &cc);
                        float r0 = a2 * cc - a3 * sn;
                        float r1 = a2 * sn + a3 * cc;
                        a2 = r0; a3 = r1;
                    }
                }
                *(uint32_t*)(C16 + (size_t)row0 * N + col) = pack_fp16(a0, a1);
                *(uint32_t*)(C16 + (size_t)(row0 + 8) * N + col) = pack_fp16(a2, a3);
            } else {
                *(float2*)(C32 + (size_t)row0 * N + col) = make_float2(a0, a1);
                *(float2*)(C32 + (size_t)(row0 + 8) * N + col) = make_float2(a2, a3);
            }
        }
    }
}

// ============================================================
// fp32 -> fp16 convert
// ============================================================
__global__ void convert_fp16_kernel(const float* __restrict__ src,
                                    __half* __restrict__ hi, int n4)
{
    int i = blockIdx.x * blockDim.x + threadIdx.x;
    if (i >= n4) return;
    float4 v = ((const float4*)src)[i];
    __half2* hp = (__half2*)hi;
    hp[2 * i]     = __halves2half2(__float2half_rn(v.x), __float2half_rn(v.y));
    hp[2 * i + 1] = __halves2half2(__float2half_rn(v.z), __float2half_rn(v.w));
}

// ============================================================
// HMMA flash attention (fp16 single-pass), 2 CTAs/SM:
// Br=128 (8 warps x 16 rows), Bc=64.
// scores = Qh·Kh ; O += Ph·Vh. Output -> fp16.
// Heavy (large-qb) tiles scheduled first via index reversal.
// ============================================================
#define QROWB 272
#define FA_QH  0
#define FA_ST0 34816
#define FA_STB 34816          // Kh + Vh per stage
#define FA_KH  0
#define FA_VH  17408
#define FA_SMEM (34816 + 2 * 34816)   // 104448

__global__ __launch_bounds__(256, 2) void fa_hmma_kernel(
    const __half* __restrict__ qh, __half* __restrict__ oh)
{
    extern __shared__ char smem[];
    const uint32_t sb = smem_to_u32(smem);
    const int tid = threadIdx.x;
    const int lane = tid & 31, w = tid >> 5;
    const int b = blockIdx.z, h = blockIdx.y;
    const int qb = gridDim.x - 1 - blockIdx.x;   // heavy tiles first
    const int kvh = h >> 2;
    const int q0 = qb * 128;
    const int rowbase = b * SEQLEN;

    // Q tile: 128 rows x 16 chunks = 2048 -> 8 iters
    #pragma unroll
    for (int l = 0; l < 8; l++) {
        int u = tid + l * 256;
        int r = (u >> 4) & 127;
        int ch = u & 15;
        const __half* src = qh +
            (size_t)(rowbase + q0 + r) * QKVDIM + h * HD + ch * 8;
        cp_async16(sb + FA_QH + r * QROWB + ch * 16, src);
    }
    // KV stage: Kh + Vh = 2048 chunks -> 8 iters
    auto load_kv = [&](int t, int s) {
        const int k0 = t * 64;
        const uint32_t stb = sb + FA_ST0 + s * FA_STB;
        #pragma unroll
        for (int l = 0; l < 8; l++) {
            int u = tid + l * 256;
            int sel = u >> 10;            // 0 Kh, 1 Vh
            int r = (u >> 4) & 63;
            int ch = u & 15;
            int gcol = sel ? (QDIM + KVDIM + kvh * HD) : (QDIM + kvh * HD);
            const __half* src = qh +
                (size_t)(rowbase + k0 + r) * QKVDIM + gcol + ch * 8;
            cp_async16(stb + sel * 17408 + r * QROWB + ch * 16, src);
        }
    };

    const int tmax = 2 * qb + 2;
    load_kv(0, 0);
    cp_commit();

    const float CEXP = 0.12751742f;       // (1/sqrt(128)) * log2(e)
    float m2[2] = {-1e30f, -1e30f};
    float l2[2] = {0.f, 0.f};
    float O[16][4];
    #pragma unroll
    for (int i = 0; i < 16; i++)
        #pragma unroll
        for (int v = 0; v < 4; v++) O[i][v] = 0.f;

    const int qrow0 = q0 + w * 16;

    for (int t = 0; t < tmax; t++) {
        if (t + 1 < tmax) load_kv(t + 1, (t + 1) & 1);
        cp_commit();
        cp_wait1();
        __syncthreads();

        const int k0 = t * 64;
        const uint32_t stb = sb + FA_ST0 + (t & 1) * FA_STB;

        if (k0 <= qrow0 + 15) {
            // ---------- scores S = Qh Kh^T ----------
            float S[8][4];
            #pragma unroll
            for (int i = 0; i < 8; i++)
                #pragma unroll
                for (int v = 0; v < 4; v++) S[i][v] = 0.f;

            const uint32_t qa = sb + FA_QH + (w * 16 + (lane & 15)) * QROWB +
                                ((lane >> 4) * 16);
            const uint32_t ka = stb + FA_KH + ((lane & 15)) * QROWB +
                                ((lane >> 4) * 16);
            #pragma unroll
            for (int kc = 0; kc < 8; kc++) {
                uint32_t A0[4];
                ldm_x4(A0, qa + kc * 32);
                #pragma unroll
                for (int g = 0; g < 4; g++) {
                    uint32_t B[4];
                    ldm_x4(B, ka + kc * 32 + g * 16 * QROWB);
                    mma_fp16(S[2 * g],     A0, B[0], B[2]);
                    mma_fp16(S[2 * g + 1], A0, B[1], B[3]);
                }
            }

            // ---------- causal mask ----------
            if (k0 + 63 > qrow0) {
                const int r0 = qrow0 + (lane >> 2);
                #pragma unroll
                for (int nt = 0; nt < 8; nt++) {
                    const int c0 = k0 + nt * 8 + (lane & 3) * 2;
                    if (c0     > r0)     S[nt][0] = -1e30f;
                    if (c0 + 1 > r0)     S[nt][1] = -1e30f;
                    if (c0     > r0 + 8) S[nt][2] = -1e30f;
                    if (c0 + 1 > r0 + 8) S[nt][3] = -1e30f;
                }
            }

            // ---------- online softmax ----------
            #pragma unroll
            for (int r = 0; r < 2; r++) {
                const int i0 = r * 2;
                float rmax = -1e30f;
                #pragma unroll
                for (int nt = 0; nt < 8; nt++)
                    rmax = fmaxf(rmax, fmaxf(S[nt][i0], S[nt][i0 + 1]));
                rmax = fmaxf(rmax, __shfl_xor_sync(0xffffffffu, rmax, 1));
                rmax = fmaxf(rmax, __shfl_xor_sync(0xffffffffu, rmax, 2));
                const float mnew = fmaxf(m2[r], rmax);
                const float corr = ex2f((m2[r] - mnew) * CEXP);
                m2[r] = mnew;
                float psum = 0.f;
                #pragma unroll
                for (int nt = 0; nt < 8; nt++) {
                    float p0 = ex2f((S[nt][i0]     - mnew) * CEXP);
                    float p1 = ex2f((S[nt][i0 + 1] - mnew) * CEXP);
                    S[nt][i0] = p0; S[nt][i0 + 1] = p1;
                    psum += p0 + p1;
                }
                psum += __shfl_xor_sync(0xffffffffu, psum, 1);
                psum += __shfl_xor_sync(0xffffffffu, psum, 2);
                l2[r] = l2[r] * corr + psum;
                #pragma unroll
                for (int nt = 0; nt < 16; nt++) {
                    O[nt][i0]     *= corr;
                    O[nt][i0 + 1] *= corr;
                }
            }

            // ---------- PV: O += Ph Vh ----------
            #pragma unroll
            for (int j = 0; j < 4; j++) {
                uint32_t Ph[4];
                #pragma unroll
                for (int q = 0; q < 2; q++) {
                    const int nt = 2 * j + q;
                    Ph[2 * q]     = pack_fp16(S[nt][0], S[nt][1]);
                    Ph[2 * q + 1] = pack_fp16(S[nt][2], S[nt][3]);
                }
                const int vrow = j * 16 + (lane & 7) + ((lane >> 3) & 1) * 8;
                #pragma unroll
                for (int n = 0; n < 8; n++) {
                    uint32_t va = stb + FA_VH + vrow * QROWB +
                                  (n * 16 + (lane >> 4) * 8) * 2;
                    uint32_t Bv[4];
                    ldm_x4_t(Bv, va);
                    mma_fp16(O[2 * n],     Ph, Bv[0], Bv[1]);
                    mma_fp16(O[2 * n + 1], Ph, Bv[2], Bv[3]);
                }
            }
        }
        __syncthreads();
    }

    // ---------- epilogue: normalize, convert to fp16 ----------
    #pragma unroll
    for (int r = 0; r < 2; r++) {
        float inv = 1.0f / l2[r];
        const int row = rowbase + qrow0 + (lane >> 2) + r * 8;
        const size_t off = (size_t)row * DMODEL + h * HD + (lane & 3) * 2;
        #pragma unroll
        for (int nt = 0; nt < 16; nt++) {
            float f0 = O[nt][2 * r] * inv;
            float f1 = O[nt][2 * r + 1] * inv;
            *(uint32_t*)(oh + off + nt * 8) = pack_fp16(f0, f1);
        }
    }
}

// ============================================================
// launch
// ============================================================
extern "C" void kernel_launch(void* const* d_in, const int* in_sizes, int n_in,
                              void* d_out, int out_size)
{
    (void)in_sizes; (void)n_in; (void)out_size;
    const float* x      = (const float*)d_in[0];
    const float* w_qkv  = (const float*)d_in[1];
    const float* b_qkv  = (const float*)d_in[2];
    const float* w_o    = (const float*)d_in[3];
    const float* b_o    = (const float*)d_in[4];
    float* out = (float*)d_out;

    __half *xh, *wqh, *woh, *ah, *qh;
    cudaGetSymbolAddress((void**)&xh,  g_xh);
    cudaGetSymbolAddress((void**)&wqh, g_wqkvh);
    cudaGetSymbolAddress((void**)&woh, g_woh);
    cudaGetSymbolAddress((void**)&ah,  g_ah);
    cudaGetSymbolAddress((void**)&qh,  g_qh);

    cudaFuncSetAttribute(hmma_gemm_kernel<true>,
                         cudaFuncAttributeMaxDynamicSharedMemorySize, HSMEM);
    cudaFuncSetAttribute(hmma_gemm_kernel<false>,
                         cudaFuncAttributeMaxDynamicSharedMemorySize, HSMEM);
    cudaFuncSetAttribute(fa_hmma_kernel,
                         cudaFuncAttributeMaxDynamicSharedMemorySize, FA_SMEM);

    // 0) convert x and weights to fp16
    {
        int n4 = (MROWS * DMODEL) / 4;
        convert_fp16_kernel<<<n4 / 256, 256>>>(x, xh, n4);
        int w4 = (QKVDIM * DMODEL) / 4;
        convert_fp16_kernel<<<w4 / 256, 256>>>(w_qkv, wqh, w4);
        int o4 = (DMODEL * DMODEL) / 4;
        convert_fp16_kernel<<<o4 / 256, 256>>>(w_o, woh, o4);
    }

    // 1) QKV projection + fused bias/RoPE/fp16 -> g_qh
    hmma_gemm_kernel<true><<<dim3(QKVDIM / HBN, MROWS / HBM), 128, HSMEM>>>(
        xh, wqh, b_qkv, nullptr, qh, MROWS, QKVDIM, DMODEL);

    // 2) fp16 flash attention -> g_ah (fp16)
    fa_hmma_kernel<<<dim3(SEQLEN / 128, NHEADS, BATCH), 256, FA_SMEM>>>(
        qh, ah);

    // 3) O projection (fp16) -> fp32 out
    hmma_gemm_kernel<false><<<dim3(DMODEL / HBN, MROWS / HBM), 128, HSMEM>>>(
        ah, woh, b_o, out, nullptr, MROWS, DMODEL, DMODEL);
}